// round 1
// baseline (speedup 1.0000x reference)
#include <cuda_runtime.h>

// Per-row cosine similarity:
//   out[i] = dot(q_i, d_i) / (||q_i|| * ||d_i||),  N = 262144 rows, D = 256 fp32.
// Pure streaming, HBM-bound. One warp per row; each lane handles 8 floats
// (2x float4) of each input -> coalesced 128B transactions, 4 independent
// vector loads in flight per warp.

#define DIM 256

__global__ __launch_bounds__(256, 8)
void cosine_rows_kernel(const float4* __restrict__ q,
                        const float4* __restrict__ d,
                        float* __restrict__ out,
                        int n_rows) {
    const int warp_in_block = threadIdx.x >> 5;
    const int lane = threadIdx.x & 31;
    const int row = blockIdx.x * (blockDim.x >> 5) + warp_in_block;
    if (row >= n_rows) return;

    // Row base in float4 units: 256 floats = 64 float4 per row.
    const int base = row * (DIM / 4);

    // Lane loads float4 at [lane] and [lane + 32]  (two 128B-coalesced sweeps).
    float4 q0 = __ldg(&q[base + lane]);
    float4 q1 = __ldg(&q[base + lane + 32]);
    float4 d0 = __ldg(&d[base + lane]);
    float4 d1 = __ldg(&d[base + lane + 32]);

    float qq = q0.x * q0.x + q0.y * q0.y + q0.z * q0.z + q0.w * q0.w
             + q1.x * q1.x + q1.y * q1.y + q1.z * q1.z + q1.w * q1.w;
    float dd = d0.x * d0.x + d0.y * d0.y + d0.z * d0.z + d0.w * d0.w
             + d1.x * d1.x + d1.y * d1.y + d1.z * d1.z + d1.w * d1.w;
    float qd = q0.x * d0.x + q0.y * d0.y + q0.z * d0.z + q0.w * d0.w
             + q1.x * d1.x + q1.y * d1.y + q1.z * d1.z + q1.w * d1.w;

    // Butterfly reduce three partials across the warp.
    #pragma unroll
    for (int off = 16; off > 0; off >>= 1) {
        qq += __shfl_xor_sync(0xFFFFFFFFu, qq, off);
        dd += __shfl_xor_sync(0xFFFFFFFFu, dd, off);
        qd += __shfl_xor_sync(0xFFFFFFFFu, qd, off);
    }

    if (lane == 0) {
        out[row] = qd * rsqrtf(qq * dd);
    }
}

extern "C" void kernel_launch(void* const* d_in, const int* in_sizes, int n_in,
                              void* d_out, int out_size) {
    const float4* q = (const float4*)d_in[0];
    const float4* d = (const float4*)d_in[1];
    float* out = (float*)d_out;

    const int n_rows = in_sizes[0] / DIM;  // 262144

    const int threads = 256;               // 8 warps -> 8 rows per block
    const int rows_per_block = threads / 32;
    const int blocks = (n_rows + rows_per_block - 1) / rows_per_block;

    cosine_rows_kernel<<<blocks, threads>>>(q, d, out, n_rows);
}